// round 5
// baseline (speedup 1.0000x reference)
#include <cuda_runtime.h>
#include <math.h>
#include <stdint.h>

// Problem constants
constexpr int kB   = 4;
constexpr int kN   = 1024;
constexpr int kHID = 256;
constexpr int kNH  = 8;
constexpr int kROWS = kB * kN;          // 4096
constexpr int kT    = 8192;             // bias table resolution
constexpr int kQT   = 64;               // queries per CTA
constexpr int kKT   = 128;              // keys per tile

// ---- smem layout (floats) for attn ----
// Qs[32][68], Ks[128][33], Vs[128][36], PU (P[64][129] | red 4*2113),
// ck[128], mk[128], m[64], l[64], corr[64], cq[64]
constexpr int OFF_QS  = 0;
constexpr int OFF_KS  = 2176;
constexpr int OFF_VS  = 6400;
constexpr int OFF_PU  = 11008;
constexpr int OFF_CK  = 19460;
constexpr int OFF_MK  = 19588;
constexpr int OFF_M   = 19716;
constexpr int OFF_L   = 19780;
constexpr int OFF_CR  = 19844;
constexpr int OFF_CQ  = 19908;
constexpr int ATTN_SMEM = 19972 * 4;    // 79888 bytes

// ---------------- scratch (no allocations allowed) ----------------
__device__ float g_xln[kROWS * kHID];        // layernormed x
__device__ float g_qkv[kROWS * 3 * kHID];    // qkv projection
__device__ float g_tab[kT * kNH];            // bias table (pre-scaled by log2e)
__device__ float g_ao [kROWS * kHID];        // attention output (pre-proj)

// ---------------- LayerNorm ----------------
__global__ void ln_kernel(const float* __restrict__ hin,
                          const float* __restrict__ gamma,
                          const float* __restrict__ beta)
{
    __shared__ float red[16];
    int row = blockIdx.x, t = threadIdx.x;
    float x = hin[(size_t)row * kHID + t];
    float s = x, s2 = x * x;
    #pragma unroll
    for (int off = 16; off; off >>= 1) {
        s  += __shfl_xor_sync(0xffffffffu, s,  off);
        s2 += __shfl_xor_sync(0xffffffffu, s2, off);
    }
    if ((t & 31) == 0) { red[t >> 5] = s; red[8 + (t >> 5)] = s2; }
    __syncthreads();
    float sum = 0.f, sum2 = 0.f;
    #pragma unroll
    for (int i = 0; i < 8; i++) { sum += red[i]; sum2 += red[8 + i]; }
    float mu  = sum * (1.0f / 256.0f);
    float var = sum2 * (1.0f / 256.0f) - mu * mu;
    float r   = rsqrtf(var + 1e-5f);
    g_xln[(size_t)row * kHID + t] = (x - mu) * r * gamma[t] + beta[t];
}

// ---------------- bias-table build: f(d) for d in [-1,1], 8192 pts ----------------
__global__ void __launch_bounds__(256) tab_kernel(
    const float* __restrict__ Wb1, const float* __restrict__ bb1,
    const float* __restrict__ Wb2, const float* __restrict__ bb2,
    const float* __restrict__ Wb3, const float* __restrict__ bb3)
{
    __shared__ float w1[64], c1[64], w2[64 * 64], c2[64], w3[64 * 8], c3[8];
    int t = threadIdx.x;
    if (t < 64) { w1[t] = Wb1[t]; c1[t] = bb1[t]; c2[t] = bb2[t]; }
    if (t < 8)  c3[t] = bb3[t];
    for (int i = t; i < 4096; i += 256) w2[i] = Wb2[i];
    for (int i = t; i < 512;  i += 256) w3[i] = Wb3[i];
    __syncthreads();

    int idx = blockIdx.x * 256 + t;
    float d = -1.0f + 2.0f * (float)idx / (float)(kT - 1);

    float h1[64];
    #pragma unroll
    for (int u = 0; u < 64; u++) {
        float a = fmaf(d, w1[u], c1[u]);
        h1[u] = a / (1.0f + expf(-a));           // silu
    }
    float acc[8];
    #pragma unroll
    for (int m = 0; m < 8; m++) acc[m] = c3[m];
    for (int u2 = 0; u2 < 64; u2++) {
        float a = c2[u2];
        #pragma unroll
        for (int u = 0; u < 64; u++) a = fmaf(h1[u], w2[u * 64 + u2], a);
        float sv = a / (1.0f + expf(-a));        // silu
        #pragma unroll
        for (int m = 0; m < 8; m++) acc[m] = fmaf(sv, w3[u2 * 8 + m], acc[m]);
    }
    const float LOG2E = 1.4426950408889634f;     // fold into table for exp2 softmax
    #pragma unroll
    for (int m = 0; m < 8; m++) g_tab[idx * 8 + m] = acc[m] * LOG2E;
}

// ---------------- generic fp32 GEMM: C[M,Nc] = A[M,K] @ W[K,Nc] + bias (+resid) ----------------
__global__ void __launch_bounds__(256) gemm64(
    const float* __restrict__ A, const float* __restrict__ W,
    const float* __restrict__ bias, const float* __restrict__ resid,
    float* __restrict__ C, int M, int Nc, int K)
{
    __shared__ float As[16][64];
    __shared__ float Bs[16][64];
    int t  = threadIdx.x;
    int n0 = blockIdx.x * 64, m0 = blockIdx.y * 64;
    int tm = t >> 4, tn = t & 15;
    int am = t >> 2, ak4 = (t & 3) * 4;
    int bk = t >> 4, bn4 = (t & 15) * 4;

    float acc[4][4] = {};
    for (int k0 = 0; k0 < K; k0 += 16) {
        float4 av = *(const float4*)(A + (size_t)(m0 + am) * K + k0 + ak4);
        float4 bv = *(const float4*)(W + (size_t)(k0 + bk) * Nc + n0 + bn4);
        As[ak4 + 0][am] = av.x; As[ak4 + 1][am] = av.y;
        As[ak4 + 2][am] = av.z; As[ak4 + 3][am] = av.w;
        *(float4*)&Bs[bk][bn4] = bv;
        __syncthreads();
        #pragma unroll
        for (int k = 0; k < 16; k++) {
            float4 a4 = *(const float4*)&As[k][tm * 4];
            float4 b4 = *(const float4*)&Bs[k][tn * 4];
            float ar[4] = {a4.x, a4.y, a4.z, a4.w};
            float br[4] = {b4.x, b4.y, b4.z, b4.w};
            #pragma unroll
            for (int i = 0; i < 4; i++)
                #pragma unroll
                for (int j = 0; j < 4; j++)
                    acc[i][j] = fmaf(ar[i], br[j], acc[i][j]);
        }
        __syncthreads();
    }
    #pragma unroll
    for (int i = 0; i < 4; i++) {
        int gm = m0 + tm * 4 + i;
        #pragma unroll
        for (int j = 0; j < 4; j++) {
            int gn = n0 + tn * 4 + j;
            float v = acc[i][j] + bias[gn];
            if (resid) v += resid[(size_t)gm * Nc + gn];
            C[(size_t)gm * Nc + gn] = v;
        }
    }
}

// ---------------- fused flash attention, register-tiled (GEMM-style) ----------------
// CTA = (qtile=64, head, batch); 256 threads; 8 key-tiles of 128.
// QK: lane tile 4q x 8k.  AV: lane tile 4q x 8d with 4-way k-split (kc class).
__global__ void __launch_bounds__(256, 2) attn_kernel(
    const float* __restrict__ coord, const int* __restrict__ mask)
{
    extern __shared__ float sm[];
    float* Qs  = sm + OFF_QS;     // [32][68], d-major, pre-scaled Q
    float* Ks  = sm + OFF_KS;     // [128][33], row-major
    float* Vs  = sm + OFF_VS;     // [128][36], row-major (float4-aligned rows)
    float* PU  = sm + OFF_PU;     // P[64][129]  |  red: kc stride 2113, q stride 33
    float* ck  = sm + OFF_CK;     // key coords
    int*   mkk = (int*)(sm + OFF_MK);
    float* msm = sm + OFF_M;
    float* lsm = sm + OFF_L;
    float* csm = sm + OFF_CR;
    float* cqs = sm + OFF_CQ;

    const int qt = blockIdx.x, h = blockIdx.y, b = blockIdx.z;
    const int q0 = qt * kQT;
    const int t  = threadIdx.x;

    const int tq = t >> 4;           // 0..15 : 4-query group (QK and AV share this)
    const int tk = t & 15;           // 0..15 : 8-key group (QK), k = tk + 16j
    const int kc = t & 3;            // 0..3  : AV k-class
    const int td = (t >> 2) & 3;     // 0..3  : AV 8-d group

    const float QSCALE = 1.4426950408889634f / 5.656854249492381f; // log2e/sqrt(32)

    // ---- one-time: stage Q (transposed, pre-scaled), init m/l, cache cq ----
    for (int idx = t; idx < kQT * 32; idx += 256) {
        int q = idx >> 5, d = idx & 31;
        Qs[d * 68 + q] = g_qkv[((size_t)(b * kN + q0 + q)) * 768 + h * 32 + d] * QSCALE;
    }
    if (t < 64) {
        msm[t] = -1e30f;
        lsm[t] = 0.f;
        cqs[t] = coord[b * kN + q0 + t];
    }

    float o[4][8];
    #pragma unroll
    for (int i = 0; i < 4; i++)
        #pragma unroll
        for (int jj = 0; jj < 8; jj++) o[i][jj] = 0.f;

    for (int j0 = 0; j0 < kN; j0 += kKT) {
        // ---- stage K/V tiles + key coords/mask ----
        if (t < 128) {
            ck[t]  = coord[b * kN + j0 + t];
            mkk[t] = mask [b * kN + j0 + t];
        }
        #pragma unroll
        for (int it = 0; it < 4; it++) {
            int idx = t + it * 256;
            int j = idx >> 3, d4 = (idx & 7) << 2;
            const float* rowp = g_qkv + ((size_t)(b * kN + j0 + j)) * 768 + h * 32 + d4;
            float4 k4 = *(const float4*)(rowp + 256);
            float4 v4 = *(const float4*)(rowp + 512);
            Ks[j * 33 + d4 + 0] = k4.x; Ks[j * 33 + d4 + 1] = k4.y;
            Ks[j * 33 + d4 + 2] = k4.z; Ks[j * 33 + d4 + 3] = k4.w;
            *(float4*)&Vs[j * 36 + d4] = v4;
        }
        __syncthreads();

        // ---- QK^T: S[4q x 8k] per lane, k strided 16 for bank-free LDS ----
        float acc[4][8];
        #pragma unroll
        for (int i = 0; i < 4; i++)
            #pragma unroll
            for (int j = 0; j < 8; j++) acc[i][j] = 0.f;
        #pragma unroll 8
        for (int d = 0; d < 32; d++) {
            float4 q4 = *(const float4*)&Qs[d * 68 + tq * 4];
            float kf[8];
            #pragma unroll
            for (int j = 0; j < 8; j++) kf[j] = Ks[(tk + 16 * j) * 33 + d];
            float qa[4] = {q4.x, q4.y, q4.z, q4.w};
            #pragma unroll
            for (int i = 0; i < 4; i++)
                #pragma unroll
                for (int j = 0; j < 8; j++)
                    acc[i][j] = fmaf(qa[i], kf[j], acc[i][j]);
        }
        // store raw S to smem P
        #pragma unroll
        for (int i = 0; i < 4; i++)
            #pragma unroll
            for (int j = 0; j < 8; j++)
                PU[(tq * 4 + i) * 129 + tk + 16 * j] = acc[i][j];
        __syncthreads();

        // ---- per-row: bias add + mask + online-softmax (rows r = t>>2) ----
        {
            int r  = t >> 2;
            int l4 = t & 3;
            float cq    = cqs[r];
            float m_old = msm[r];
            float tmax  = -1e30f;
            float* prow = PU + r * 129;
            #pragma unroll 4
            for (int cidx = 0; cidx < 32; cidx++) {
                int c = l4 * 8 + (cidx & 7) + (cidx >> 3) * 32;  // bank-free interleave
                float s;
                if (mkk[c] == 0) {
                    s = -1e38f;
                } else {
                    float dd = ck[c] - cq;
                    float u  = fmaf(dd, 4095.5f, 4095.5f);
                    int i0 = (int)u;
                    i0 = i0 < 0 ? 0 : (i0 > kT - 2 ? kT - 2 : i0);
                    float fr = u - (float)i0;
                    float b0 = g_tab[i0 * 8 + h];
                    float b1 = g_tab[i0 * 8 + 8 + h];
                    s = prow[c] + fmaf(fr, b1 - b0, b0);
                }
                prow[c] = s;
                tmax = fmaxf(tmax, s);
            }
            tmax = fmaxf(tmax, __shfl_xor_sync(0xffffffffu, tmax, 1));
            tmax = fmaxf(tmax, __shfl_xor_sync(0xffffffffu, tmax, 2));
            float m_new = fmaxf(m_old, tmax);
            float corr  = exp2f(m_old - m_new);
            float sum = 0.f;
            #pragma unroll 4
            for (int cidx = 0; cidx < 32; cidx++) {
                int c = l4 * 8 + (cidx & 7) + (cidx >> 3) * 32;
                float p = exp2f(prow[c] - m_new);
                prow[c] = p;
                sum += p;
            }
            sum += __shfl_xor_sync(0xffffffffu, sum, 1);
            sum += __shfl_xor_sync(0xffffffffu, sum, 2);
            if (l4 == 0) {
                msm[r] = m_new;
                lsm[r] = lsm[r] * corr + sum;
                csm[r] = corr;
            }
        }
        __syncthreads();

        // ---- rescale O, then AV: o[4q x 8d] over this thread's k-class ----
        #pragma unroll
        for (int i = 0; i < 4; i++) {
            float corr = csm[tq * 4 + i];
            #pragma unroll
            for (int jj = 0; jj < 8; jj++) o[i][jj] *= corr;
        }
        #pragma unroll 4
        for (int kk = 0; kk < 32; kk++) {
            int k = kc + kk * 4;
            float p[4];
            #pragma unroll
            for (int i = 0; i < 4; i++) p[i] = PU[(tq * 4 + i) * 129 + k];
            float4 v0 = *(const float4*)&Vs[k * 36 + td * 8];
            float4 v1 = *(const float4*)&Vs[k * 36 + td * 8 + 4];
            float vv[8] = {v0.x, v0.y, v0.z, v0.w, v1.x, v1.y, v1.z, v1.w};
            #pragma unroll
            for (int i = 0; i < 4; i++)
                #pragma unroll
                for (int jj = 0; jj < 8; jj++)
                    o[i][jj] = fmaf(p[i], vv[jj], o[i][jj]);
        }
        __syncthreads();   // P/K/V free for next tile
    }

    // ---- reduce the 4 k-class partials via smem, normalize, write out ----
    float* red = PU;   // kc stride 2113, q stride 33 (bank-conflict-free)
    #pragma unroll
    for (int i = 0; i < 4; i++)
        #pragma unroll
        for (int jj = 0; jj < 8; jj++)
            red[kc * 2113 + (tq * 4 + i) * 33 + td * 8 + jj] = o[i][jj];
    __syncthreads();
    {
        int q  = t >> 2;
        int d0 = (t & 3) * 8;
        float inv = 1.0f / lsm[q];
        float res[8];
        #pragma unroll
        for (int j = 0; j < 8; j++) {
            float s = 0.f;
            #pragma unroll
            for (int c = 0; c < 4; c++) s += red[c * 2113 + q * 33 + d0 + j];
            res[j] = s * inv;
        }
        float* orow = g_ao + ((size_t)(b * kN + q0 + q)) * 256 + h * 32 + d0;
        float4 w0 = {res[0], res[1], res[2], res[3]};
        float4 w1 = {res[4], res[5], res[6], res[7]};
        *(float4*)(orow)     = w0;
        *(float4*)(orow + 4) = w1;
    }
}

// ---------------- launch ----------------
extern "C" void kernel_launch(void* const* d_in, const int* in_sizes, int n_in,
                              void* d_out, int out_size)
{
    const float* hin   = (const float*)d_in[0];
    const float* coord = (const float*)d_in[1];
    const int*   mask  = (const int*)  d_in[2];
    const float* Wqkv  = (const float*)d_in[3];
    const float* bqkv  = (const float*)d_in[4];
    const float* Wproj = (const float*)d_in[5];
    const float* bproj = (const float*)d_in[6];
    const float* gamma = (const float*)d_in[7];
    const float* beta  = (const float*)d_in[8];
    const float* Wb1   = (const float*)d_in[9];
    const float* bb1   = (const float*)d_in[10];
    const float* Wb2   = (const float*)d_in[11];
    const float* bb2   = (const float*)d_in[12];
    const float* Wb3   = (const float*)d_in[13];
    const float* bb3   = (const float*)d_in[14];
    float* out = (float*)d_out;

    void *p_xln, *p_qkv, *p_ao;
    cudaGetSymbolAddress(&p_xln, g_xln);
    cudaGetSymbolAddress(&p_qkv, g_qkv);
    cudaGetSymbolAddress(&p_ao,  g_ao);

    cudaFuncSetAttribute(attn_kernel, cudaFuncAttributeMaxDynamicSharedMemorySize, ATTN_SMEM);

    // independent: bias table
    tab_kernel<<<kT / 256, 256>>>(Wb1, bb1, Wb2, bb2, Wb3, bb3);
    // layernorm
    ln_kernel<<<kROWS, 256>>>(hin, gamma, beta);
    // qkv = xln @ Wqkv + bqkv
    gemm64<<<dim3(768 / 64, kROWS / 64), 256>>>((const float*)p_xln, Wqkv, bqkv, nullptr,
                                                (float*)p_qkv, kROWS, 768, 256);
    // fused bias-lookup flash attention (register-tiled)
    attn_kernel<<<dim3(kN / kQT, kNH, kB), 256, ATTN_SMEM>>>(coord, mask);
    // out = h + ao @ Wproj + bproj
    gemm64<<<dim3(256 / 64, kROWS / 64), 256>>>((const float*)p_ao, Wproj, bproj, hin,
                                                out, kROWS, 256, 256);
}

// round 6
// speedup vs baseline: 1.4082x; 1.4082x over previous
#include <cuda_runtime.h>
#include <math.h>
#include <stdint.h>

typedef unsigned long long u64;

// Problem constants
constexpr int kB   = 4;
constexpr int kN   = 1024;
constexpr int kHID = 256;
constexpr int kNH  = 8;
constexpr int kROWS = kB * kN;          // 4096
constexpr int kT    = 2048;             // bias table resolution
constexpr int kQT   = 64;               // queries per CTA
constexpr int kKT   = 128;              // keys per tile

// ---- packed f32x2 helpers ----
#define PACK2(out, lo, hi) \
    asm("mov.b64 %0, {%1, %2};" : "=l"(out) : "f"(lo), "f"(hi))
#define UNPACK2(lo, hi, v) \
    asm("mov.b64 {%0, %1}, %2;" : "=f"(lo), "=f"(hi) : "l"(v))
#define FMA2(acc, a, b) \
    asm("fma.rn.f32x2 %0, %1, %2, %0;" : "+l"(acc) : "l"(a), "l"(b))
#define MUL2(out, a, b) \
    asm("mul.rn.f32x2 %0, %1, %2;" : "=l"(out) : "l"(a), "l"(b))

// ---- smem layout (floats) for attn ----
constexpr int OFF_QS  = 0;                    // Qs[32][68]
constexpr int OFF_KT  = 2176;                 // Kt[32][132]  d-major, k-pairs
constexpr int OFF_VS  = 6400;                 // Vs[128][36]
constexpr int OFF_PU  = 11008;                // P[64][132] | red 4*2113
constexpr int OFF_TB  = 19460;                // tabd float2[2048] interleaved
constexpr int OFF_CK  = 23556;                // key coords [128]
constexpr int OFF_MK  = 23684;                // key mask   [128]
constexpr int OFF_M   = 23812;                // m[64]
constexpr int OFF_L   = 23876;                // l[64]
constexpr int OFF_CR  = 23940;                // corr[64]
constexpr int OFF_CQ  = 24004;                // cq[64]
constexpr int ATTN_SMEM = 24068 * 4;          // 96272 bytes

// ---------------- scratch (no allocations allowed) ----------------
__device__ float g_xln[kROWS * kHID];        // layernormed x
__device__ float g_qkv[kROWS * 3 * kHID];    // qkv projection
__device__ float g_tab[kNH * kT];            // bias table, HEAD-MAJOR, pre-scaled log2e
__device__ float g_ao [kROWS * kHID];        // attention output (pre-proj)

// ---------------- LayerNorm ----------------
__global__ void ln_kernel(const float* __restrict__ hin,
                          const float* __restrict__ gamma,
                          const float* __restrict__ beta)
{
    __shared__ float red[16];
    int row = blockIdx.x, t = threadIdx.x;
    float x = hin[(size_t)row * kHID + t];
    float s = x, s2 = x * x;
    #pragma unroll
    for (int off = 16; off; off >>= 1) {
        s  += __shfl_xor_sync(0xffffffffu, s,  off);
        s2 += __shfl_xor_sync(0xffffffffu, s2, off);
    }
    if ((t & 31) == 0) { red[t >> 5] = s; red[8 + (t >> 5)] = s2; }
    __syncthreads();
    float sum = 0.f, sum2 = 0.f;
    #pragma unroll
    for (int i = 0; i < 8; i++) { sum += red[i]; sum2 += red[8 + i]; }
    float mu  = sum * (1.0f / 256.0f);
    float var = sum2 * (1.0f / 256.0f) - mu * mu;
    float r   = rsqrtf(var + 1e-5f);
    g_xln[(size_t)row * kHID + t] = (x - mu) * r * gamma[t] + beta[t];
}

// ---------------- bias-table build: f(d) for d in [-1,1], kT pts, head-major ----------------
__global__ void __launch_bounds__(256) tab_kernel(
    const float* __restrict__ Wb1, const float* __restrict__ bb1,
    const float* __restrict__ Wb2, const float* __restrict__ bb2,
    const float* __restrict__ Wb3, const float* __restrict__ bb3)
{
    __shared__ float w1[64], c1[64], w2[64 * 64], c2[64], w3[64 * 8], c3[8];
    int t = threadIdx.x;
    if (t < 64) { w1[t] = Wb1[t]; c1[t] = bb1[t]; c2[t] = bb2[t]; }
    if (t < 8)  c3[t] = bb3[t];
    for (int i = t; i < 4096; i += 256) w2[i] = Wb2[i];
    for (int i = t; i < 512;  i += 256) w3[i] = Wb3[i];
    __syncthreads();

    int idx = blockIdx.x * 256 + t;
    float d = -1.0f + 2.0f * (float)idx / (float)(kT - 1);

    float h1[64];
    #pragma unroll
    for (int u = 0; u < 64; u++) {
        float a = fmaf(d, w1[u], c1[u]);
        h1[u] = a / (1.0f + expf(-a));           // silu
    }
    float acc[8];
    #pragma unroll
    for (int m = 0; m < 8; m++) acc[m] = c3[m];
    for (int u2 = 0; u2 < 64; u2++) {
        float a = c2[u2];
        #pragma unroll
        for (int u = 0; u < 64; u++) a = fmaf(h1[u], w2[u * 64 + u2], a);
        float sv = a / (1.0f + expf(-a));        // silu
        #pragma unroll
        for (int m = 0; m < 8; m++) acc[m] = fmaf(sv, w3[u2 * 8 + m], acc[m]);
    }
    const float LOG2E = 1.4426950408889634f;
    #pragma unroll
    for (int m = 0; m < 8; m++) g_tab[m * kT + idx] = acc[m] * LOG2E;
}

// ---------------- fp32 GEMM with packed FFMA2: C = A@W + bias (+resid) ----------------
__global__ void __launch_bounds__(256) gemm64(
    const float* __restrict__ A, const float* __restrict__ W,
    const float* __restrict__ bias, const float* __restrict__ resid,
    float* __restrict__ C, int M, int Nc, int K)
{
    __shared__ float As[16][64];
    __shared__ float Bs[16][64];
    int t  = threadIdx.x;
    int n0 = blockIdx.x * 64, m0 = blockIdx.y * 64;
    int tm = t >> 4, tn = t & 15;
    int am = t >> 2, ak4 = (t & 3) * 4;
    int bk = t >> 4, bn4 = (t & 15) * 4;

    u64 acc2[4][2] = {};
    for (int k0 = 0; k0 < K; k0 += 16) {
        float4 av = *(const float4*)(A + (size_t)(m0 + am) * K + k0 + ak4);
        float4 bv = *(const float4*)(W + (size_t)(k0 + bk) * Nc + n0 + bn4);
        As[ak4 + 0][am] = av.x; As[ak4 + 1][am] = av.y;
        As[ak4 + 2][am] = av.z; As[ak4 + 3][am] = av.w;
        *(float4*)&Bs[bk][bn4] = bv;
        __syncthreads();
        #pragma unroll
        for (int k = 0; k < 16; k++) {
            float4 a4 = *(const float4*)&As[k][tm * 4];
            const u64* bp = (const u64*)&Bs[k][tn * 4];
            u64 b01 = bp[0], b23 = bp[1];
            float ar[4] = {a4.x, a4.y, a4.z, a4.w};
            #pragma unroll
            for (int i = 0; i < 4; i++) {
                u64 ap; PACK2(ap, ar[i], ar[i]);
                FMA2(acc2[i][0], ap, b01);
                FMA2(acc2[i][1], ap, b23);
            }
        }
        __syncthreads();
    }
    #pragma unroll
    for (int i = 0; i < 4; i++) {
        int gm = m0 + tm * 4 + i;
        float cv[4];
        UNPACK2(cv[0], cv[1], acc2[i][0]);
        UNPACK2(cv[2], cv[3], acc2[i][1]);
        #pragma unroll
        for (int j = 0; j < 4; j++) {
            int gn = n0 + tn * 4 + j;
            float v = cv[j] + bias[gn];
            if (resid) v += resid[(size_t)gm * Nc + gn];
            C[(size_t)gm * Nc + gn] = v;
        }
    }
}

// ---------------- fused flash attention, FFMA2-packed register tiles ----------------
// CTA = (qtile=64, head, batch); 256 threads; 8 key-tiles of 128.
__global__ void __launch_bounds__(256, 2) attn_kernel(
    const float* __restrict__ coord, const int* __restrict__ mask)
{
    extern __shared__ float sm[];
    float* Qs  = sm + OFF_QS;     // [32][68] d-major
    float* Kt  = sm + OFF_KT;     // [32][132] d-major (keys along row, pairs)
    float* Vs  = sm + OFF_VS;     // [128][36] k-major
    float* PU  = sm + OFF_PU;     // P[64][132] | red (kc*2113 + q*33 + d)
    float* TB  = sm + OFF_TB;     // interleaved table pairs (f[i], f[i+1])
    float* ck  = sm + OFF_CK;
    int*   mkk = (int*)(sm + OFF_MK);
    float* msm = sm + OFF_M;
    float* lsm = sm + OFF_L;
    float* csm = sm + OFF_CR;
    float* cqs = sm + OFF_CQ;

    const int qt = blockIdx.x, h = blockIdx.y, b = blockIdx.z;
    const int q0 = qt * kQT;
    const int t  = threadIdx.x;

    const int tq = t >> 4;           // 0..15 : 4-query group
    const int tk = t & 15;           // 0..15 : key-pair group (QK)
    const int kc = t & 3;            // 0..3  : AV k-class
    const int td = (t >> 2) & 3;     // 0..3  : AV d-pair group

    const float QSCALE = 1.4426950408889634f / 5.656854249492381f; // log2e/sqrt(32)

    // ---- one-time: stage Q (d-major, pre-scaled), table pairs, init m/l ----
    for (int idx = t; idx < kQT * 32; idx += 256) {
        int q = idx >> 5, d = idx & 31;
        Qs[d * 68 + q] = g_qkv[((size_t)(b * kN + q0 + q)) * 768 + h * 32 + d] * QSCALE;
    }
    #pragma unroll
    for (int it = 0; it < 8; it++) {
        int i = t + it * 256;
        float f0 = g_tab[h * kT + i];
        float f1 = g_tab[h * kT + (i < kT - 1 ? i + 1 : kT - 1)];
        u64 pr; PACK2(pr, f0, f1);
        *(u64*)&TB[2 * i] = pr;
    }
    if (t < 64) {
        msm[t] = -1e30f;
        lsm[t] = 0.f;
        cqs[t] = coord[b * kN + q0 + t];
    }

    u64 o2[4][4] = {};   // 4 q-rows x 4 packed d-pairs (d = 2*td+8u, +1)

    for (int j0 = 0; j0 < kN; j0 += kKT) {
        // ---- stage K (transposed to d-major k-pairs) ----
        #pragma unroll
        for (int it = 0; it < 2; it++) {
            int w = t + it * 256;           // 0..511
            int p = w >> 3;                 // key pair 0..63
            int d4 = (w & 7) * 4;
            const float* r0 = g_qkv + ((size_t)(b * kN + j0 + 2 * p)) * 768 + h * 32 + d4;
            float4 k0 = *(const float4*)(r0 + 256);
            float4 k1 = *(const float4*)(r0 + 256 + 768);
            float a0[4] = {k0.x, k0.y, k0.z, k0.w};
            float a1[4] = {k1.x, k1.y, k1.z, k1.w};
            #pragma unroll
            for (int dd = 0; dd < 4; dd++) {
                u64 pr; PACK2(pr, a0[dd], a1[dd]);
                *(u64*)&Kt[(d4 + dd) * 132 + 2 * p] = pr;
            }
        }
        // ---- stage V (k-major) ----
        #pragma unroll
        for (int it = 0; it < 4; it++) {
            int idx = t + it * 256;
            int j = idx >> 3, d4 = (idx & 7) * 4;
            const float* rowp = g_qkv + ((size_t)(b * kN + j0 + j)) * 768 + h * 32 + d4;
            *(float4*)&Vs[j * 36 + d4] = *(const float4*)(rowp + 512);
        }
        if (t < 128) {
            ck[t]  = coord[b * kN + j0 + t];
            mkk[t] = mask [b * kN + j0 + t];
        }
        __syncthreads();

        // ---- QK^T: acc2[4 q][4 key-pairs], keys 2(tk+16jp), +1 ----
        u64 acc2[4][4] = {};
        #pragma unroll 4
        for (int d = 0; d < 32; d++) {
            float4 q4 = *(const float4*)&Qs[d * 68 + tq * 4];
            const float* krow = &Kt[d * 132 + 2 * tk];
            u64 kp0 = *(const u64*)(krow);
            u64 kp1 = *(const u64*)(krow + 32);
            u64 kp2 = *(const u64*)(krow + 64);
            u64 kp3 = *(const u64*)(krow + 96);
            float qa[4] = {q4.x, q4.y, q4.z, q4.w};
            #pragma unroll
            for (int i = 0; i < 4; i++) {
                u64 qq; PACK2(qq, qa[i], qa[i]);
                FMA2(acc2[i][0], qq, kp0);
                FMA2(acc2[i][1], qq, kp1);
                FMA2(acc2[i][2], qq, kp2);
                FMA2(acc2[i][3], qq, kp3);
            }
        }
        // store raw S (packed pairs) to P
        #pragma unroll
        for (int i = 0; i < 4; i++) {
            float* prow = &PU[(tq * 4 + i) * 132 + 2 * tk];
            *(u64*)(prow)      = acc2[i][0];
            *(u64*)(prow + 32) = acc2[i][1];
            *(u64*)(prow + 64) = acc2[i][2];
            *(u64*)(prow + 96) = acc2[i][3];
        }
        __syncthreads();

        // ---- per-row: bias add + mask + online-softmax (row r = t>>2) ----
        {
            int r  = t >> 2;
            int l4 = t & 3;
            float cq    = cqs[r];
            float m_old = msm[r];
            float tmax  = -1e30f;
            float* prow = PU + r * 132;
            #pragma unroll 4
            for (int cidx = 0; cidx < 32; cidx++) {
                int c = l4 * 8 + (((cidx & 7) + r) & 7) + ((cidx >> 3) << 5);
                float s;
                if (mkk[c] == 0) {
                    s = -1e38f;
                } else {
                    float dd = ck[c] - cq;
                    float u  = fmaf(dd, 1023.5f, 1023.5f);
                    int i0 = (int)u;
                    i0 = i0 < 0 ? 0 : (i0 > kT - 2 ? kT - 2 : i0);
                    float fr = u - (float)i0;
                    float b0, b1;
                    u64 bb = *(const u64*)&TB[2 * i0];
                    UNPACK2(b0, b1, bb);
                    s = prow[c] + fmaf(fr, b1 - b0, b0);
                }
                prow[c] = s;
                tmax = fmaxf(tmax, s);
            }
            tmax = fmaxf(tmax, __shfl_xor_sync(0xffffffffu, tmax, 1));
            tmax = fmaxf(tmax, __shfl_xor_sync(0xffffffffu, tmax, 2));
            float m_new = fmaxf(m_old, tmax);
            float corr  = exp2f(m_old - m_new);
            float sum = 0.f;
            #pragma unroll 4
            for (int cidx = 0; cidx < 32; cidx++) {
                int c = l4 * 8 + (((cidx & 7) + r) & 7) + ((cidx >> 3) << 5);
                float p = exp2f(prow[c] - m_new);
                prow[c] = p;
                sum += p;
            }
            sum += __shfl_xor_sync(0xffffffffu, sum, 1);
            sum += __shfl_xor_sync(0xffffffffu, sum, 2);
            if (l4 == 0) {
                msm[r] = m_new;
                lsm[r] = lsm[r] * corr + sum;
                csm[r] = corr;
            }
        }
        __syncthreads();

        // ---- rescale O (packed), then AV with conflict-free k ordering ----
        #pragma unroll
        for (int i = 0; i < 4; i++) {
            float corr = csm[tq * 4 + i];
            u64 cp; PACK2(cp, corr, corr);
            #pragma unroll
            for (int u = 0; u < 4; u++) MUL2(o2[i][u], o2[i][u], cp);
        }
        #pragma unroll 4
        for (int kk = 0; kk < 32; kk++) {
            int s = (kk + 2 * td + tq) & 31;
            int k = kc + 4 * s;
            float p[4];
            #pragma unroll
            for (int i = 0; i < 4; i++) p[i] = PU[(tq * 4 + i) * 132 + k];
            const float* vrow = &Vs[k * 36 + 2 * td];
            u64 v0 = *(const u64*)(vrow);
            u64 v1 = *(const u64*)(vrow + 8);
            u64 v2 = *(const u64*)(vrow + 16);
            u64 v3 = *(const u64*)(vrow + 24);
            #pragma unroll
            for (int i = 0; i < 4; i++) {
                u64 pp; PACK2(pp, p[i], p[i]);
                FMA2(o2[i][0], pp, v0);
                FMA2(o2[i][1], pp, v1);
                FMA2(o2[i][2], pp, v2);
                FMA2(o2[i][3], pp, v3);
            }
        }
        __syncthreads();   // P/K/V free for next tile
    }

    // ---- reduce 4 k-class partials via smem, normalize, write out ----
    float* red = PU;   // kc stride 2113, q stride 33
    #pragma unroll
    for (int i = 0; i < 4; i++) {
        #pragma unroll
        for (int u = 0; u < 4; u++) {
            float lo, hi;
            UNPACK2(lo, hi, o2[i][u]);
            int d = 8 * u + 2 * td;
            red[kc * 2113 + (tq * 4 + i) * 33 + d]     = lo;
            red[kc * 2113 + (tq * 4 + i) * 33 + d + 1] = hi;
        }
    }
    __syncthreads();
    {
        int q  = t >> 2;
        int d0 = (t & 3) * 8;
        float inv = 1.0f / lsm[q];
        float res[8];
        #pragma unroll
        for (int j = 0; j < 8; j++) {
            float s = 0.f;
            #pragma unroll
            for (int c = 0; c < 4; c++) s += red[c * 2113 + q * 33 + d0 + j];
            res[j] = s * inv;
        }
        float* orow = g_ao + ((size_t)(b * kN + q0 + q)) * 256 + h * 32 + d0;
        float4 w0 = {res[0], res[1], res[2], res[3]};
        float4 w1 = {res[4], res[5], res[6], res[7]};
        *(float4*)(orow)     = w0;
        *(float4*)(orow + 4) = w1;
    }
}

// ---------------- launch ----------------
extern "C" void kernel_launch(void* const* d_in, const int* in_sizes, int n_in,
                              void* d_out, int out_size)
{
    const float* hin   = (const float*)d_in[0];
    const float* coord = (const float*)d_in[1];
    const int*   mask  = (const int*)  d_in[2];
    const float* Wqkv  = (const float*)d_in[3];
    const float* bqkv  = (const float*)d_in[4];
    const float* Wproj = (const float*)d_in[5];
    const float* bproj = (const float*)d_in[6];
    const float* gamma = (const float*)d_in[7];
    const float* beta  = (const float*)d_in[8];
    const float* Wb1   = (const float*)d_in[9];
    const float* bb1   = (const float*)d_in[10];
    const float* Wb2   = (const float*)d_in[11];
    const float* bb2   = (const float*)d_in[12];
    const float* Wb3   = (const float*)d_in[13];
    const float* bb3   = (const float*)d_in[14];
    float* out = (float*)d_out;

    void *p_xln, *p_qkv, *p_ao;
    cudaGetSymbolAddress(&p_xln, g_xln);
    cudaGetSymbolAddress(&p_qkv, g_qkv);
    cudaGetSymbolAddress(&p_ao,  g_ao);

    cudaFuncSetAttribute(attn_kernel, cudaFuncAttributeMaxDynamicSharedMemorySize, ATTN_SMEM);

    // independent: bias table
    tab_kernel<<<kT / 256, 256>>>(Wb1, bb1, Wb2, bb2, Wb3, bb3);
    // layernorm
    ln_kernel<<<kROWS, 256>>>(hin, gamma, beta);
    // qkv = xln @ Wqkv + bqkv
    gemm64<<<dim3(768 / 64, kROWS / 64), 256>>>((const float*)p_xln, Wqkv, bqkv, nullptr,
                                                (float*)p_qkv, kROWS, 768, 256);
    // fused bias-lookup flash attention (FFMA2 register-tiled)
    attn_kernel<<<dim3(kN / kQT, kNH, kB), 256, ATTN_SMEM>>>(coord, mask);
    // out = h + ao @ Wproj + bproj
    gemm64<<<dim3(256 / 64, kROWS / 64), 256>>>((const float*)p_ao, Wproj, bproj, hin,
                                                out, kROWS, 256, 256);
}